// round 1
// baseline (speedup 1.0000x reference)
#include <cuda_runtime.h>

// Problem constants (from reference setup_inputs)
#define BB 8
#define TT 4096
#define DD 1024
#define CC 64                 // number of T-chunks
#define LL 64                 // chunk length (TT / CC)
#define LANES (BB * DD)       // 8192 scalar lanes
#define VLANES (LANES / 4)    // 2048 float4 lanes
#define DV (DD / 4)           // 256 float4 per row

// Scratch (static device globals; no allocation allowed)
__device__ float g_S[CC * LANES];     // per-chunk aggregate h_L(0):  2 MB
__device__ float g_Hin[CC * LANES];   // per-chunk incoming h:        2 MB
__device__ float g_hfinal_scratch[LANES];

__device__ __forceinline__ float sigmoidf_(float v) {
    return 1.0f / (1.0f + __expf(-v));
}
__device__ __forceinline__ float siluf_(float v) {
    return v * sigmoidf_(v);
}

// ---------------------------------------------------------------------------
// Pass 1: each (chunk, vec-lane) computes S_c = h_L(0) for its chunk.
// s_{i} = lam * (s_{i-1} + silu(x_i)) + b, s_0 = 0
// ---------------------------------------------------------------------------
__global__ __launch_bounds__(256) void e55_pass1(
    const float* __restrict__ x,
    const float* __restrict__ bias,
    const float* __restrict__ loglam)
{
    int tid = blockIdx.x * blockDim.x + threadIdx.x;   // [0, CC*VLANES)
    int c   = tid / VLANES;
    int l   = tid % VLANES;
    int bi  = l / DV;
    int dv  = l % DV;

    float lam = sigmoidf_(loglam[0]);

    const float4* __restrict__ Xr = (const float4*)x;
    long base = ((long)bi * TT + (long)c * LL) * DV + dv;

    float4 bv = ((const float4*)bias)[dv];
    float4 s = make_float4(0.f, 0.f, 0.f, 0.f);

    for (int ib = 0; ib < LL; ib += 8) {
        float4 xv[8];
        #pragma unroll
        for (int j = 0; j < 8; j++)
            xv[j] = Xr[base + (long)(ib + j) * DV];
        #pragma unroll
        for (int j = 0; j < 8; j++) {
            float4 xs;
            xs.x = siluf_(xv[j].x);
            xs.y = siluf_(xv[j].y);
            xs.z = siluf_(xv[j].z);
            xs.w = siluf_(xv[j].w);
            s.x = fmaf(lam, s.x + xs.x, bv.x);
            s.y = fmaf(lam, s.y + xs.y, bv.y);
            s.z = fmaf(lam, s.z + xs.z, bv.z);
            s.w = fmaf(lam, s.w + xs.w, bv.w);
        }
    }

    ((float4*)g_S)[(long)c * VLANES + l] = s;
}

// ---------------------------------------------------------------------------
// Pass 2: sequential carry scan over chunks per scalar lane.
// Hin[0] = h0;  Hin[c] = lam^L * Hin[c-1] + S[c-1];  h_final written out.
// All S values are prefetched to registers (L2 resident) -> huge MLP.
// ---------------------------------------------------------------------------
__global__ __launch_bounds__(256) void e55_pass2(
    const float* __restrict__ h0,
    const float* __restrict__ loglam,
    float* __restrict__ hfinal)
{
    int j = blockIdx.x * blockDim.x + threadIdx.x;   // [0, LANES)

    float lam = sigmoidf_(loglam[0]);
    float lamL = 1.0f;
    #pragma unroll
    for (int i = 0; i < LL; i++) lamL *= lam;

    float sArr[CC];
    #pragma unroll
    for (int c = 0; c < CC; c++)
        sArr[c] = g_S[c * LANES + j];

    float h = h0[j];
    #pragma unroll
    for (int c = 0; c < CC; c++) {
        g_Hin[c * LANES + j] = h;
        h = fmaf(lamL, h, sArr[c]);
    }
    hfinal[j] = h;
}

// ---------------------------------------------------------------------------
// Pass 3: re-scan each chunk with correct incoming h, apply self-gate, store.
// out_t = h_t * silu(h_t) = h_t^2 * sigmoid(h_t)
// ---------------------------------------------------------------------------
__global__ __launch_bounds__(256) void e55_pass3(
    const float* __restrict__ x,
    const float* __restrict__ bias,
    const float* __restrict__ loglam,
    float* __restrict__ out)
{
    int tid = blockIdx.x * blockDim.x + threadIdx.x;   // [0, CC*VLANES)
    int c   = tid / VLANES;
    int l   = tid % VLANES;
    int bi  = l / DV;
    int dv  = l % DV;

    float lam = sigmoidf_(loglam[0]);

    const float4* __restrict__ Xr = (const float4*)x;
    float4* __restrict__ Or = (float4*)out;
    long base = ((long)bi * TT + (long)c * LL) * DV + dv;

    float4 bv = ((const float4*)bias)[dv];
    float4 h = ((const float4*)g_Hin)[(long)c * VLANES + l];

    for (int ib = 0; ib < LL; ib += 8) {
        float4 xv[8];
        #pragma unroll
        for (int j = 0; j < 8; j++)
            xv[j] = Xr[base + (long)(ib + j) * DV];
        #pragma unroll
        for (int j = 0; j < 8; j++) {
            float4 xs;
            xs.x = siluf_(xv[j].x);
            xs.y = siluf_(xv[j].y);
            xs.z = siluf_(xv[j].z);
            xs.w = siluf_(xv[j].w);
            h.x = fmaf(lam, h.x + xs.x, bv.x);
            h.y = fmaf(lam, h.y + xs.y, bv.y);
            h.z = fmaf(lam, h.z + xs.z, bv.z);
            h.w = fmaf(lam, h.w + xs.w, bv.w);
            float4 g;
            g.x = h.x * h.x * sigmoidf_(h.x);
            g.y = h.y * h.y * sigmoidf_(h.y);
            g.z = h.z * h.z * sigmoidf_(h.z);
            g.w = h.w * h.w * sigmoidf_(h.w);
            Or[base + (long)(ib + j) * DV] = g;
        }
    }
}

// ---------------------------------------------------------------------------
// Launch
// Inputs (metadata order): x [B,T,D] f32, h0 [B,D] f32, log_lambda [1] f32,
//                          b [D] f32
// Output: output [B,T,D] then h_final [B,D], concatenated, f32
// ---------------------------------------------------------------------------
extern "C" void kernel_launch(void* const* d_in, const int* in_sizes, int n_in,
                              void* d_out, int out_size)
{
    const float* x      = (const float*)d_in[0];
    const float* h0     = (const float*)d_in[1];
    const float* loglam = (const float*)d_in[2];
    const float* bias   = (const float*)d_in[3];
    float* out = (float*)d_out;

    const long n_output = (long)BB * TT * DD;

    // h_final destination: tail of d_out if there is space, else scratch.
    float* hfinal;
    if ((long)out_size >= n_output + LANES) {
        hfinal = out + n_output;
    } else {
        // resolve address of device scratch
        void* p = nullptr;
        cudaGetSymbolAddress(&p, g_hfinal_scratch);
        hfinal = (float*)p;
    }

    dim3 blk(256);
    dim3 grid1((CC * VLANES) / 256);   // 512 blocks
    dim3 grid2(LANES / 256);           // 32 blocks

    e55_pass1<<<grid1, blk>>>(x, bias, loglam);
    e55_pass2<<<grid2, blk>>>(h0, loglam, hfinal);
    e55_pass3<<<grid1, blk>>>(x, bias, loglam, out);
}

// round 2
// speedup vs baseline: 1.2451x; 1.2451x over previous
#include <cuda_runtime.h>

// Problem constants (from reference setup_inputs)
#define BB 8
#define TT 4096
#define DD 1024
#define CC 128                // number of T-chunks
#define LL 32                 // chunk length (TT / CC)
#define LANES (BB * DD)       // 8192 scalar lanes
#define VLANES (LANES / 4)    // 2048 float4 lanes
#define DV (DD / 4)           // 256 float4 per row

// Scratch (static device globals; no allocation allowed)
__device__ float g_S[CC * LANES];     // per-chunk aggregate h_L(0):  4 MB
__device__ float g_Hin[CC * LANES];   // per-chunk incoming h:        4 MB
__device__ float g_hfinal_scratch[LANES];

// sigmoid via EX2 + RCP approx (2 MUFU, ~3 fma ops; ~1e-7 rel err)
__device__ __forceinline__ float fsig_(float v) {
    float e = __expf(-v);                 // FMUL + MUFU.EX2
    return __fdividef(1.0f, 1.0f + e);    // FADD + MUFU.RCP (+mul)
}
__device__ __forceinline__ float fsilu_(float v) {
    float e = __expf(-v);
    return __fdividef(v, 1.0f + e);
}

// ---------------------------------------------------------------------------
// Pass 1: each (chunk, vec-lane) computes S_c = h_L(0) for its chunk.
// s_i = lam * (s_{i-1} + silu(x_i)) + b, s_0 = 0
// ---------------------------------------------------------------------------
__global__ __launch_bounds__(256) void e55_pass1(
    const float* __restrict__ x,
    const float* __restrict__ bias,
    const float* __restrict__ loglam)
{
    int tid = blockIdx.x * blockDim.x + threadIdx.x;   // [0, CC*VLANES)
    int c   = tid >> 11;          // / VLANES
    int l   = tid & (VLANES - 1);
    int bi  = l >> 8;             // / DV
    int dv  = l & (DV - 1);

    float lam = fsig_(loglam[0]);

    const float4* __restrict__ xp =
        (const float4*)x + ((bi * TT + c * LL) * DV + dv);

    float4 bv = ((const float4*)bias)[dv];
    float4 s = make_float4(0.f, 0.f, 0.f, 0.f);

    for (int ib = 0; ib < LL; ib += 8) {
        float4 xv[8];
        #pragma unroll
        for (int j = 0; j < 8; j++)
            xv[j] = __ldcs(xp + j * DV);
        xp += 8 * DV;
        #pragma unroll
        for (int j = 0; j < 8; j++) {
            float4 xs;
            xs.x = fsilu_(xv[j].x);
            xs.y = fsilu_(xv[j].y);
            xs.z = fsilu_(xv[j].z);
            xs.w = fsilu_(xv[j].w);
            s.x = fmaf(lam, s.x + xs.x, bv.x);
            s.y = fmaf(lam, s.y + xs.y, bv.y);
            s.z = fmaf(lam, s.z + xs.z, bv.z);
            s.w = fmaf(lam, s.w + xs.w, bv.w);
        }
    }

    ((float4*)g_S)[c * VLANES + l] = s;
}

// ---------------------------------------------------------------------------
// Pass 2: sequential carry scan over chunks per scalar lane.
// Hin[0] = h0;  Hin[c] = lam^L * Hin[c-1] + S[c-1];  h_final written out.
// S / Hin are L2-resident (4 MB each). Batched prefetch for MLP.
// ---------------------------------------------------------------------------
__global__ __launch_bounds__(128) void e55_pass2(
    const float* __restrict__ h0,
    const float* __restrict__ loglam,
    float* __restrict__ hfinal)
{
    int j = blockIdx.x * blockDim.x + threadIdx.x;   // [0, LANES)

    float lam = fsig_(loglam[0]);
    // lam^LL via 5 squarings (LL = 32)
    float lamL = lam;
    #pragma unroll
    for (int i = 0; i < 5; i++) lamL *= lamL;

    float h = h0[j];
    for (int cb = 0; cb < CC; cb += 16) {
        float sv[16];
        #pragma unroll
        for (int k = 0; k < 16; k++)
            sv[k] = g_S[(cb + k) * LANES + j];
        #pragma unroll
        for (int k = 0; k < 16; k++) {
            g_Hin[(cb + k) * LANES + j] = h;
            h = fmaf(lamL, h, sv[k]);
        }
    }
    hfinal[j] = h;
}

// ---------------------------------------------------------------------------
// Pass 3: re-scan each chunk with correct incoming h, apply self-gate, store.
// out_t = h_t * silu(h_t) = h_t^2 * sigmoid(h_t)
// ---------------------------------------------------------------------------
__global__ __launch_bounds__(256) void e55_pass3(
    const float* __restrict__ x,
    const float* __restrict__ bias,
    const float* __restrict__ loglam,
    float* __restrict__ out)
{
    int tid = blockIdx.x * blockDim.x + threadIdx.x;   // [0, CC*VLANES)
    int c   = tid >> 11;
    int l   = tid & (VLANES - 1);
    int bi  = l >> 8;
    int dv  = l & (DV - 1);

    float lam = fsig_(loglam[0]);

    int base = (bi * TT + c * LL) * DV + dv;
    const float4* __restrict__ xp = (const float4*)x + base;
    float4* __restrict__ op = (float4*)out + base;

    float4 bv = ((const float4*)bias)[dv];
    float4 h = ((const float4*)g_Hin)[c * VLANES + l];

    for (int ib = 0; ib < LL; ib += 8) {
        float4 xv[8];
        #pragma unroll
        for (int j = 0; j < 8; j++)
            xv[j] = __ldcs(xp + j * DV);
        xp += 8 * DV;
        #pragma unroll
        for (int j = 0; j < 8; j++) {
            float4 xs;
            xs.x = fsilu_(xv[j].x);
            xs.y = fsilu_(xv[j].y);
            xs.z = fsilu_(xv[j].z);
            xs.w = fsilu_(xv[j].w);
            h.x = fmaf(lam, h.x + xs.x, bv.x);
            h.y = fmaf(lam, h.y + xs.y, bv.y);
            h.z = fmaf(lam, h.z + xs.z, bv.z);
            h.w = fmaf(lam, h.w + xs.w, bv.w);
            float4 g;
            g.x = h.x * h.x * fsig_(h.x);
            g.y = h.y * h.y * fsig_(h.y);
            g.z = h.z * h.z * fsig_(h.z);
            g.w = h.w * h.w * fsig_(h.w);
            __stcs(op + j * DV, g);
        }
        op += 8 * DV;
    }
}

// ---------------------------------------------------------------------------
// Launch
// Inputs (metadata order): x [B,T,D] f32, h0 [B,D] f32, log_lambda [1] f32,
//                          b [D] f32
// Output: output [B,T,D] then h_final [B,D], concatenated, f32
// ---------------------------------------------------------------------------
extern "C" void kernel_launch(void* const* d_in, const int* in_sizes, int n_in,
                              void* d_out, int out_size)
{
    const float* x      = (const float*)d_in[0];
    const float* h0     = (const float*)d_in[1];
    const float* loglam = (const float*)d_in[2];
    const float* bias   = (const float*)d_in[3];
    float* out = (float*)d_out;

    const long n_output = (long)BB * TT * DD;

    // h_final destination: tail of d_out if there is space, else scratch.
    float* hfinal;
    if ((long)out_size >= n_output + LANES) {
        hfinal = out + n_output;
    } else {
        void* p = nullptr;
        cudaGetSymbolAddress(&p, g_hfinal_scratch);
        hfinal = (float*)p;
    }

    dim3 blk(256);
    dim3 grid1((CC * VLANES) / 256);   // 1024 blocks
    dim3 blk2(128);
    dim3 grid2(LANES / 128);           // 64 blocks

    e55_pass1<<<grid1, blk>>>(x, bias, loglam);
    e55_pass2<<<grid2, blk2>>>(h0, loglam, hfinal);
    e55_pass3<<<grid1, blk>>>(x, bias, loglam, out);
}